// round 15
// baseline (speedup 1.0000x reference)
#include <cuda_runtime.h>
#include <cuda_fp16.h>
#include <cstdint>

#define NN 100000
#define NE 1600000
#define DH 128
#define NTILES ((NN + 127) / 128)
#define SB 72      // padded smem row stride (fp16): 144B -> conflict-free ldmatrix
#define TSZ 18432  // one 128 x SB fp16 tile image, bytes
#define SM_TOTAL (4 * TSZ)   // A0, A1, B0, B1 (double buffered)

typedef unsigned int u32;
typedef unsigned short u16;

// ---------------- scratch (device globals: no allocation allowed) -----------
__device__ int    g_deg[NN];          // zero-init; re-zeroed by k_scan_fuse each run
__device__ int    g_rowoff[NN];       // INCLUSIVE scan: rowoff[w] = end of row w
__device__ int    g_rank[NE];         // per-edge rank within its dst row (from prep)
__device__ int    g_blocksum[512];
__device__ int    g_csr_src[NE];
__device__ __half g_aggh[(size_t)NN * DH];  // fp16 aggregation result
__device__ __half g_xh  [(size_t)NN * DH];  // fp16 copy of x   (gather + root L0)
__device__ __half g_h1h [(size_t)NN * DH];  // fp16 h1          (gather + root L1)
// 4 fp16 weight images, [n][k] row-major 128x128: Wn0, Wr0, Wn1, Wr1 (transposed)
__device__ u16 g_wimg[4][16384];

__device__ __forceinline__ u32 smem_u32(const void* p) {
    u32 a;
    asm("{ .reg .u64 t; cvta.to.shared.u64 t, %1; cvt.u32.u64 %0, t; }"
        : "=r"(a) : "l"(p));
    return a;
}
__device__ __forceinline__ void cpa16(u32 dst, const void* src, int srcsz) {
    asm volatile("cp.async.ca.shared.global [%0], [%1], 16, %2;"
                 :: "r"(dst), "l"(src), "r"(srcsz) : "memory");
}
__device__ __forceinline__ void cpa_commit() {
    asm volatile("cp.async.commit_group;" ::: "memory");
}
template <int N>
__device__ __forceinline__ void cpa_wait() {
    asm volatile("cp.async.wait_group %0;" :: "n"(N) : "memory");
}

// ---------------- fused prep: x->fp16, weights, degree count + edge rank ----
// g_deg is zero at entry (zero-init first run; k_scan_fuse re-zeroes every run).
// The atomic's return value IS the edge's rank within its dst row -> scatter
// later needs no atomics at all.
__global__ void k_prep(const float* __restrict__ x, const int* __restrict__ dst,
                       const float* __restrict__ Wn0, const float* __restrict__ Wr0,
                       const float* __restrict__ Wn1, const float* __restrict__ Wr1) {
    int i = blockIdx.x * blockDim.x + threadIdx.x;
    if (i < NN * DH / 4) {                              // x -> fp16 (float4 groups)
        float4 v = *(const float4*)(x + (size_t)i * 4);
        __half2 h0 = __floats2half2_rn(v.x, v.y);
        __half2 h1 = __floats2half2_rn(v.z, v.w);
        uint2 p;
        p.x = *(u32*)&h0; p.y = *(u32*)&h1;
        *(uint2*)(g_xh + (size_t)i * 4) = p;
    }
    if (i < 65536) {                                    // weights: transpose + fp16
        int mat = i >> 14, e = i & 16383;
        int n = e >> 7, k = e & 127;
        const float* W = (mat == 0) ? Wn0 : (mat == 1) ? Wr0 : (mat == 2) ? Wn1 : Wr1;
        g_wimg[mat][n * 128 + k] = __half_as_ushort(__float2half_rn(W[k * 128 + n]));
    }
    if (i < NE) {
        int p = atomicAdd(&g_deg[dst[i]], 1);           // degree count + rank
        g_rank[i] = p;
    }
}

// ---------------- CSR build --------------------------------------------------
// INCLUSIVE block-local scan: g_rowoff[i] = sum_{j<=i within block} deg[j].
__global__ void k_scan_block() {
    __shared__ int s[256];
    int t = threadIdx.x;
    int i = blockIdx.x * 256 + t;
    int v = (i < NN) ? g_deg[i] : 0;
    s[t] = v; __syncthreads();
#pragma unroll
    for (int off = 1; off < 256; off <<= 1) {
        int tv = (t >= off) ? s[t - off] : 0;
        __syncthreads();
        s[t] += tv;
        __syncthreads();
    }
    if (i < NN) g_rowoff[i] = s[t];          // inclusive: row-end position
    if (t == 255) g_blocksum[blockIdx.x] = s[255];
}
// 391 blocks x 512 threads: every block scans all block sums, applies its own
// offset, and zeroes g_deg for the next graph replay.
__global__ void k_scan_fuse(int nblocks) {
    __shared__ int s[512];
    int t = threadIdx.x;
    int v = (t < nblocks) ? g_blocksum[t] : 0;
    s[t] = v; __syncthreads();
    for (int off = 1; off < 512; off <<= 1) {
        int tv = (t >= off) ? s[t - off] : 0;
        __syncthreads();
        s[t] += tv;
        __syncthreads();
    }
    int boff = s[blockIdx.x] - g_blocksum[blockIdx.x];   // exclusive prefix of blocks
    if (t < 256) {
        int i = blockIdx.x * 256 + t;
        if (i < NN) {
            g_rowoff[i] += boff;
            g_deg[i] = 0;
        }
    }
}
// ATOMIC-FREE scatter: slot = row_begin(dst) + rank.  4 edges/thread,
// full-size grid (concurrency is what the L2 path wants). NE % 4 == 0.
__global__ void k_scatter(const int* __restrict__ src, const int* __restrict__ dst) {
    int i = blockIdx.x * blockDim.x + threadIdx.x;
    int e = i * 4;
    if (e < NE) {
        int4 d  = *(const int4*)(dst + e);
        int4 s  = *(const int4*)(src + e);
        int4 rk = *(const int4*)(g_rank + e);
        int b0 = d.x ? g_rowoff[d.x - 1] : 0;
        int b1 = d.y ? g_rowoff[d.y - 1] : 0;
        int b2 = d.z ? g_rowoff[d.z - 1] : 0;
        int b3 = d.w ? g_rowoff[d.w - 1] : 0;
        g_csr_src[b0 + rk.x] = s.x;
        g_csr_src[b1 + rk.y] = s.y;
        g_csr_src[b2 + rk.z] = s.z;
        g_csr_src[b3 + rk.w] = s.w;
    }
}

// ---------------- mean aggregation: fp16 gather -> fp16 out (R12 form) ------
// One warp per node; independent per-edge fp32 accumulation, MLP = 8.
// R13/R14 proved: never reduce gather/atomic thread parallelism.
__global__ void k_agg(const __half* __restrict__ feat, __half* __restrict__ out) {
    int w    = (blockIdx.x * blockDim.x + threadIdx.x) >> 5;
    int lane = threadIdx.x & 31;
    if (w >= NN) return;
    int beg = (w > 0) ? g_rowoff[w - 1] : 0;
    int end = g_rowoff[w];
    float ax = 0.f, ay = 0.f, az = 0.f, aw = 0.f;
    const size_t lo = (size_t)lane * 4;
    int e = beg;
    for (; e + 8 <= end; e += 8) {                 // MLP = 8 on the gather
        uint2 r[8];
#pragma unroll
        for (int q = 0; q < 8; q++) {
            int s = g_csr_src[e + q];
            r[q] = *(const uint2*)(feat + (size_t)s * DH + lo);
        }
#pragma unroll
        for (int q = 0; q < 8; q++) {
            float2 f0 = __half22float2(*(__half2*)&r[q].x);
            float2 f1 = __half22float2(*(__half2*)&r[q].y);
            ax += f0.x; ay += f0.y; az += f1.x; aw += f1.y;
        }
    }
    if (e + 4 <= end) {                            // one 4-block tail
        uint2 r[4];
#pragma unroll
        for (int q = 0; q < 4; q++) {
            int s = g_csr_src[e + q];
            r[q] = *(const uint2*)(feat + (size_t)s * DH + lo);
        }
#pragma unroll
        for (int q = 0; q < 4; q++) {
            float2 f0 = __half22float2(*(__half2*)&r[q].x);
            float2 f1 = __half22float2(*(__half2*)&r[q].y);
            ax += f0.x; ay += f0.y; az += f1.x; aw += f1.y;
        }
        e += 4;
    }
    for (; e < end; e++) {
        int s0 = g_csr_src[e];
        uint2 r = *(const uint2*)(feat + (size_t)s0 * DH + lo);
        float2 f0 = __half22float2(*(__half2*)&r.x);
        float2 f1 = __half22float2(*(__half2*)&r.y);
        ax += f0.x; ay += f0.y; az += f1.x; aw += f1.y;
    }
    int deg = end - beg;
    float inv = 1.0f / (float)(deg > 1 ? deg : 1);
    __half2 o0 = __floats2half2_rn(ax * inv, ay * inv);
    __half2 o1 = __floats2half2_rn(az * inv, aw * inv);
    uint2 p;
    p.x = *(u32*)&o0; p.y = *(u32*)&o1;
    *(uint2*)(out + (size_t)w * DH + lo) = p;
}

// ---------------- MMA primitives ---------------------------------------------
__device__ __forceinline__ void ldm_x4(u32& r0, u32& r1, u32& r2, u32& r3, u32 addr) {
    asm volatile("ldmatrix.sync.aligned.m8n8.x4.shared.b16 {%0,%1,%2,%3}, [%4];"
                 : "=r"(r0), "=r"(r1), "=r"(r2), "=r"(r3) : "r"(addr));
}
__device__ __forceinline__ void mma16816(float* c, const u32* a, u32 b0, u32 b1) {
    asm volatile(
        "mma.sync.aligned.m16n8k16.row.col.f32.f16.f16.f32 "
        "{%0,%1,%2,%3},{%4,%5,%6,%7},{%8,%9},{%0,%1,%2,%3};"
        : "+f"(c[0]), "+f"(c[1]), "+f"(c[2]), "+f"(c[3])
        : "r"(a[0]), "r"(a[1]), "r"(a[2]), "r"(a[3]), "r"(b0), "r"(b1));
}

// ---------------- GEMM core: fp16, K=256 in 4 chunks, cp.async 2-buffer -----
// acc += AggH @ Wn + RootH @ Wr   (chunks 0,1 = agg/Wn; 2,3 = root/Wr)
// dsm layout: A0 | A1 | B0 | B1, each TSZ bytes; chunk kc uses buffer kc&1.
__device__ __forceinline__ void gemm_core(
    char* dsm, const __half* __restrict__ AggH, const __half* __restrict__ RootH,
    const u16* __restrict__ Bn, const u16* __restrict__ Br,
    int blockRow, int tid, int lane, int warpR, int warpC,
    float acc[2][8][4])
{
    const u32 a_b[2] = { smem_u32(dsm), smem_u32(dsm + TSZ) };
    const u32 b_b[2] = { smem_u32(dsm + 2 * TSZ), smem_u32(dsm + 3 * TSZ) };
    const int arow = tid >> 1, acol = (tid & 1) * 32;
    const int agrow = blockRow + arow;
    const bool inb = (agrow < NN);
    const size_t arow_off = (size_t)(inb ? agrow : 0) * DH;
    const int asz = inb ? 16 : 0;     // cp.async src-size: 0 -> zero-fill

    auto issue = [&](int kc) {
        const __half* srcF = (kc < 2) ? AggH : RootH;
        const u16*    Bimg = (kc < 2) ? Bn   : Br;
        const int koff = (kc & 1) * 64;
        const int buf = kc & 1;
        u32 adst = a_b[buf] + (u32)(arow * SB + acol) * 2;
        const __half* rp = srcF + arow_off + koff + acol;
#pragma unroll
        for (int j = 0; j < 4; j++) cpa16(adst + j * 16, rp + j * 8, asz);
        u32 bdst = b_b[buf] + (u32)(arow * SB + acol) * 2;
        const u16* bp = Bimg + arow * 128 + koff + acol;
#pragma unroll
        for (int j = 0; j < 4; j++) cpa16(bdst + j * 16, bp + j * 8, 16);
        cpa_commit();
    };

    issue(0);
#pragma unroll
    for (int kc = 0; kc < 4; kc++) {
        if (kc < 3) { issue(kc + 1); cpa_wait<1>(); }
        else        { cpa_wait<0>(); }
        __syncthreads();

        const u32 ab = a_b[kc & 1], bb = b_b[kc & 1];
#pragma unroll
        for (int ks = 0; ks < 4; ks++) {
            int k0 = ks * 16;
            u32 afrag[2][4];
#pragma unroll
            for (int mi = 0; mi < 2; mi++) {
                int rowA = warpR + mi * 16 + (lane & 15);
                int colA = k0 + ((lane >> 4) << 3);
                ldm_x4(afrag[mi][0], afrag[mi][1], afrag[mi][2], afrag[mi][3],
                       ab + (u32)(rowA * SB + colA) * 2);
            }
            u32 bfrag[4][4];
#pragma unroll
            for (int pj = 0; pj < 4; pj++) {
                int nB = warpC + pj * 16 + ((lane >> 4) << 3) + (lane & 7);
                int kB = k0 + (lane & 8);
                ldm_x4(bfrag[pj][0], bfrag[pj][1], bfrag[pj][2], bfrag[pj][3],
                       bb + (u32)(nB * SB + kB) * 2);
            }
#pragma unroll
            for (int mi = 0; mi < 2; mi++)
#pragma unroll
                for (int nj = 0; nj < 8; nj++) {
                    const u32* bp = bfrag[nj >> 1];
                    u32 b0 = (nj & 1) ? bp[2] : bp[0];
                    u32 b1 = (nj & 1) ? bp[3] : bp[1];
                    mma16816(acc[mi][nj], afrag[mi], b0, b1);
                }
        }
        __syncthreads();   // buffer kc&1 free before issue(kc+2) overwrites it
    }
}

// ---------------- GEMM kernel: mid layer (fp16 hidden out) -------------------
__global__ __launch_bounds__(256, 2)
void k_gemm_mid(const __half* __restrict__ AggH, const __half* __restrict__ RootH,
                const u16* __restrict__ Bn, const u16* __restrict__ Br,
                const float* __restrict__ bias, __half* __restrict__ HoutH)
{
    extern __shared__ char dsm[];
    const int tid = threadIdx.x, wid = tid >> 5, lane = tid & 31;
    const int blockRow = blockIdx.x * 128;
    const int warpR = (wid & 3) * 32, warpC = (wid >> 2) * 64;

    float acc[2][8][4];
#pragma unroll
    for (int i = 0; i < 2; i++)
#pragma unroll
        for (int j = 0; j < 8; j++)
#pragma unroll
            for (int q = 0; q < 4; q++) acc[i][j][q] = 0.f;

    gemm_core(dsm, AggH, RootH, Bn, Br, blockRow, tid, lane, warpR, warpC, acc);

    const int g = lane >> 2, tg = lane & 3;
#pragma unroll
    for (int mi = 0; mi < 2; mi++) {
        int row0 = blockRow + warpR + mi * 16 + g;
        int row1 = row0 + 8;
#pragma unroll
        for (int nj = 0; nj < 8; nj++) {
            int col = warpC + nj * 8 + tg * 2;
            float b0v = bias[col], b1v = bias[col + 1];
            if (row0 < NN)
                *(__half2*)(HoutH + (size_t)row0 * DH + col) =
                    __floats2half2_rn(fmaxf(acc[mi][nj][0] + b0v, 0.f),
                                      fmaxf(acc[mi][nj][1] + b1v, 0.f));
            if (row1 < NN)
                *(__half2*)(HoutH + (size_t)row1 * DH + col) =
                    __floats2half2_rn(fmaxf(acc[mi][nj][2] + b0v, 0.f),
                                      fmaxf(acc[mi][nj][3] + b1v, 0.f));
        }
    }
}

// ---------------- GEMM kernel: last layer + fused head -----------------------
__global__ __launch_bounds__(256, 2)
void k_gemm_head(const __half* __restrict__ AggH, const __half* __restrict__ RootH,
                 const u16* __restrict__ Bn, const u16* __restrict__ Br,
                 const float* __restrict__ bias,
                 const float* __restrict__ Wh, const float* __restrict__ bh,
                 float* __restrict__ out)
{
    extern __shared__ char dsm[];
    __shared__ float HeadPart[2][128];
    const int tid = threadIdx.x, wid = tid >> 5, lane = tid & 31;
    const int blockRow = blockIdx.x * 128;
    const int warpR = (wid & 3) * 32, warpC = (wid >> 2) * 64;

    float acc[2][8][4];
#pragma unroll
    for (int i = 0; i < 2; i++)
#pragma unroll
        for (int j = 0; j < 8; j++)
#pragma unroll
            for (int q = 0; q < 4; q++) acc[i][j][q] = 0.f;

    gemm_core(dsm, AggH, RootH, Bn, Br, blockRow, tid, lane, warpR, warpC, acc);

    const int g = lane >> 2, tg = lane & 3;
    float p0[2] = {0.f, 0.f}, p1[2] = {0.f, 0.f};
#pragma unroll
    for (int mi = 0; mi < 2; mi++) {
#pragma unroll
        for (int nj = 0; nj < 8; nj++) {
            int col = warpC + nj * 8 + tg * 2;
            float b0v = bias[col], b1v = bias[col + 1];
            float w0 = Wh[col], w1 = Wh[col + 1];
            p0[mi] += fmaxf(acc[mi][nj][0] + b0v, 0.f) * w0
                    + fmaxf(acc[mi][nj][1] + b1v, 0.f) * w1;
            p1[mi] += fmaxf(acc[mi][nj][2] + b0v, 0.f) * w0
                    + fmaxf(acc[mi][nj][3] + b1v, 0.f) * w1;
        }
    }
#pragma unroll
    for (int off = 1; off <= 2; off <<= 1) {
#pragma unroll
        for (int mi = 0; mi < 2; mi++) {
            p0[mi] += __shfl_xor_sync(0xFFFFFFFFu, p0[mi], off);
            p1[mi] += __shfl_xor_sync(0xFFFFFFFFu, p1[mi], off);
        }
    }
    if (tg == 0) {
#pragma unroll
        for (int mi = 0; mi < 2; mi++) {
            HeadPart[wid >> 2][warpR + mi * 16 + g]     = p0[mi];
            HeadPart[wid >> 2][warpR + mi * 16 + g + 8] = p1[mi];
        }
    }
    __syncthreads();
    if (tid < 128) {
        int r = blockRow + tid;
        if (r < NN) out[r] = HeadPart[0][tid] + HeadPart[1][tid] + bh[0];
    }
}

// ---------------- launch -----------------------------------------------------
extern "C" void kernel_launch(void* const* d_in, const int* in_sizes, int n_in,
                              void* d_out, int out_size) {
    const float* x   = (const float*)d_in[0];
    const int*   ei  = (const int*)  d_in[1];
    const int*   src = ei;
    const int*   dst = ei + NE;
    const float* Wn0 = (const float*)d_in[2];
    const float* Wr0 = (const float*)d_in[3];
    const float* b0  = (const float*)d_in[4];
    const float* Wn1 = (const float*)d_in[5];
    const float* Wr1 = (const float*)d_in[6];
    const float* b1  = (const float*)d_in[7];
    const float* Wh  = (const float*)d_in[8];
    const float* bh  = (const float*)d_in[9];
    float* out = (float*)d_out;

    __half *aggh, *xh, *h1h;
    u16* wimg;
    cudaGetSymbolAddress((void**)&aggh, g_aggh);
    cudaGetSymbolAddress((void**)&xh,   g_xh);
    cudaGetSymbolAddress((void**)&h1h,  g_h1h);
    cudaGetSymbolAddress((void**)&wimg, g_wimg);

    // idempotent, set every call (no static guards allowed)
    cudaFuncSetAttribute(k_gemm_mid,  cudaFuncAttributeMaxDynamicSharedMemorySize, SM_TOTAL);
    cudaFuncSetAttribute(k_gemm_head, cudaFuncAttributeMaxDynamicSharedMemorySize, SM_TOTAL);

    const int NB_N  = (NN + 255) / 256;            // 391
    const int NB_E4 = (NE / 4 + 255) / 256;        // 1563 (4 edges/thread, no atomics)
    const int NB_W  = (NN * 32 + 255) / 256;       // 12500 (warp per node)
    const int NB_P  = (NN * DH / 4 + 255) / 256;   // 12500 (covers NE and 65536)

    // prep (x->fp16, weights, degree count + rank) + CSR build
    k_prep      <<<NB_P, 256>>>(x, dst, Wn0, Wr0, Wn1, Wr1);
    k_scan_block<<<NB_N, 256>>>();
    k_scan_fuse <<<NB_N, 512>>>(NB_N);
    k_scatter   <<<NB_E4, 256>>>(src, dst);

    // layer 0
    k_agg     <<<NB_W, 256>>>(xh, aggh);
    k_gemm_mid<<<NTILES, 256, SM_TOTAL>>>(aggh, xh,
        wimg + 0 * 16384, wimg + 1 * 16384, b0, h1h);
    // layer 1 + fused head
    k_agg      <<<NB_W, 256>>>(h1h, aggh);
    k_gemm_head<<<NTILES, 256, SM_TOTAL>>>(aggh, h1h,
        wimg + 2 * 16384, wimg + 3 * 16384, b1, Wh, bh, out);
}

// round 16
// speedup vs baseline: 1.1710x; 1.1710x over previous
#include <cuda_runtime.h>
#include <cuda_fp16.h>
#include <cstdint>

#define NN 100000
#define NE 1600000
#define DH 128
#define NTILES ((NN + 127) / 128)
#define SB 72      // padded smem row stride (fp16): 144B -> conflict-free ldmatrix
#define TSZ 18432  // one 128 x SB fp16 tile image, bytes
#define SM_TOTAL (4 * TSZ)   // A0, A1, B0, B1 (double buffered)

typedef unsigned int u32;
typedef unsigned short u16;

// ---------------- scratch (device globals: no allocation allowed) -----------
__device__ int    g_deg[NN];          // zero-init; re-zeroed by k_scan_fuse each run
__device__ int    g_rowoff[NN];       // shifted CSR: after scatter, rowoff[w] = row-end
__device__ int    g_blocksum[512];
__device__ int    g_csr_src[NE];      // stores src*DH (premultiplied row offset)
__device__ __half g_aggh[(size_t)NN * DH];  // fp16 aggregation result
__device__ __half g_xh  [(size_t)NN * DH];  // fp16 copy of x   (gather + root L0)
__device__ __half g_h1h [(size_t)NN * DH];  // fp16 h1          (gather + root L1)
// 4 fp16 weight images, [n][k] row-major 128x128: Wn0, Wr0, Wn1, Wr1 (transposed)
__device__ u16 g_wimg[4][16384];

__device__ __forceinline__ u32 smem_u32(const void* p) {
    u32 a;
    asm("{ .reg .u64 t; cvta.to.shared.u64 t, %1; cvt.u32.u64 %0, t; }"
        : "=r"(a) : "l"(p));
    return a;
}
__device__ __forceinline__ void cpa16(u32 dst, const void* src, int srcsz) {
    asm volatile("cp.async.ca.shared.global [%0], [%1], 16, %2;"
                 :: "r"(dst), "l"(src), "r"(srcsz) : "memory");
}
__device__ __forceinline__ void cpa_commit() {
    asm volatile("cp.async.commit_group;" ::: "memory");
}
template <int N>
__device__ __forceinline__ void cpa_wait() {
    asm volatile("cp.async.wait_group %0;" :: "n"(N) : "memory");
}

// ---------------- fused prep: x->fp16, weights, edge degree count -----------
// g_deg is zero at entry (zero-init first run; k_scan_fuse re-zeroes every run).
// Degree atomic discards its return (RED path) — R15 proved capturing the
// return here destroys prep throughput.
__global__ void k_prep(const float* __restrict__ x, const int* __restrict__ dst,
                       const float* __restrict__ Wn0, const float* __restrict__ Wr0,
                       const float* __restrict__ Wn1, const float* __restrict__ Wr1) {
    int i = blockIdx.x * blockDim.x + threadIdx.x;
    if (i < NN * DH / 4) {                              // x -> fp16 (float4 groups)
        float4 v = *(const float4*)(x + (size_t)i * 4);
        __half2 h0 = __floats2half2_rn(v.x, v.y);
        __half2 h1 = __floats2half2_rn(v.z, v.w);
        uint2 p;
        p.x = *(u32*)&h0; p.y = *(u32*)&h1;
        *(uint2*)(g_xh + (size_t)i * 4) = p;
    }
    if (i < 65536) {                                    // weights: transpose + fp16
        int mat = i >> 14, e = i & 16383;
        int n = e >> 7, k = e & 127;
        const float* W = (mat == 0) ? Wn0 : (mat == 1) ? Wr0 : (mat == 2) ? Wn1 : Wr1;
        g_wimg[mat][n * 128 + k] = __half_as_ushort(__float2half_rn(W[k * 128 + n]));
    }
    if (i < NE) atomicAdd(&g_deg[dst[i]], 1);           // degree count (no return)
}

// ---------------- CSR build --------------------------------------------------
__global__ void k_scan_block() {
    __shared__ int s[256];
    int t = threadIdx.x;
    int i = blockIdx.x * 256 + t;
    int v = (i < NN) ? g_deg[i] : 0;
    s[t] = v; __syncthreads();
#pragma unroll
    for (int off = 1; off < 256; off <<= 1) {
        int tv = (t >= off) ? s[t - off] : 0;
        __syncthreads();
        s[t] += tv;
        __syncthreads();
    }
    if (i < NN) g_rowoff[i] = s[t] - v;      // block-local exclusive
    if (t == 255) g_blocksum[blockIdx.x] = s[255];
}
// 391 blocks x 512 threads: every block scans all block sums, applies its own
// offset, and zeroes g_deg for the next graph replay. (No cursor: scatter
// advances g_rowoff in place -> shifted CSR.)
__global__ void k_scan_fuse(int nblocks) {
    __shared__ int s[512];
    int t = threadIdx.x;
    int v = (t < nblocks) ? g_blocksum[t] : 0;
    s[t] = v; __syncthreads();
    for (int off = 1; off < 512; off <<= 1) {
        int tv = (t >= off) ? s[t - off] : 0;
        __syncthreads();
        s[t] += tv;
        __syncthreads();
    }
    int boff = s[blockIdx.x] - g_blocksum[blockIdx.x];   // exclusive prefix
    if (t < 256) {
        int i = blockIdx.x * 256 + t;
        if (i < NN) {
            g_rowoff[i] += boff;
            g_deg[i] = 0;
        }
    }
}
// advances g_rowoff[dst] in place; after completion rowoff[w] = end of row w,
// begin of row w = (w ? rowoff[w-1] : 0). One edge per thread — R14 proved
// atomic throughput here is concurrency-bound; keep the grid maximal.
// Stores src*DH so the gather needs no per-edge multiply.
__global__ void k_scatter(const int* __restrict__ src, const int* __restrict__ dst) {
    int e = blockIdx.x * blockDim.x + threadIdx.x;
    if (e < NE) {
        int p = atomicAdd(&g_rowoff[dst[e]], 1);
        g_csr_src[p] = src[e] * DH;
    }
}

// ---------------- mean aggregation: fp16 gather -> fp16 out -----------------
// One warp per node; independent per-edge fp32 accumulation, MLP = 8 (R12
// optimum). Indices premultiplied by DH; 8 indices fetched per iteration via
// two int4 broadcast loads (after 4-alignment peel).
__global__ void k_agg(const __half* __restrict__ feat, __half* __restrict__ out) {
    int w    = (blockIdx.x * blockDim.x + threadIdx.x) >> 5;
    int lane = threadIdx.x & 31;
    if (w >= NN) return;
    int beg = (w > 0) ? g_rowoff[w - 1] : 0;
    int end = g_rowoff[w];
    float ax = 0.f, ay = 0.f, az = 0.f, aw = 0.f;
    const size_t lo = (size_t)lane * 4;
    int e = beg;
    // peel to 4-aligned e for int4 index loads
    int alim = (beg + 3) & ~3;
    if (alim > end) alim = end;
    for (; e < alim; e++) {
        int s0 = g_csr_src[e];
        uint2 r = *(const uint2*)(feat + (size_t)(u32)s0 + lo);
        float2 f0 = __half22float2(*(__half2*)&r.x);
        float2 f1 = __half22float2(*(__half2*)&r.y);
        ax += f0.x; ay += f0.y; az += f1.x; aw += f1.y;
    }
    for (; e + 8 <= end; e += 8) {                 // MLP = 8 on the gather
        int4 i0 = *(const int4*)(g_csr_src + e);
        int4 i1 = *(const int4*)(g_csr_src + e + 4);
        int idx[8] = {i0.x, i0.y, i0.z, i0.w, i1.x, i1.y, i1.z, i1.w};
        uint2 r[8];
#pragma unroll
        for (int q = 0; q < 8; q++)
            r[q] = *(const uint2*)(feat + (size_t)(u32)idx[q] + lo);
#pragma unroll
        for (int q = 0; q < 8; q++) {
            float2 f0 = __half22float2(*(__half2*)&r[q].x);
            float2 f1 = __half22float2(*(__half2*)&r[q].y);
            ax += f0.x; ay += f0.y; az += f1.x; aw += f1.y;
        }
    }
    if (e + 4 <= end) {                            // one 4-block tail
        int4 i0 = *(const int4*)(g_csr_src + e);
        int idx[4] = {i0.x, i0.y, i0.z, i0.w};
        uint2 r[4];
#pragma unroll
        for (int q = 0; q < 4; q++)
            r[q] = *(const uint2*)(feat + (size_t)(u32)idx[q] + lo);
#pragma unroll
        for (int q = 0; q < 4; q++) {
            float2 f0 = __half22float2(*(__half2*)&r[q].x);
            float2 f1 = __half22float2(*(__half2*)&r[q].y);
            ax += f0.x; ay += f0.y; az += f1.x; aw += f1.y;
        }
        e += 4;
    }
    for (; e < end; e++) {
        int s0 = g_csr_src[e];
        uint2 r = *(const uint2*)(feat + (size_t)(u32)s0 + lo);
        float2 f0 = __half22float2(*(__half2*)&r.x);
        float2 f1 = __half22float2(*(__half2*)&r.y);
        ax += f0.x; ay += f0.y; az += f1.x; aw += f1.y;
    }
    int deg = end - beg;
    float inv = 1.0f / (float)(deg > 1 ? deg : 1);
    __half2 o0 = __floats2half2_rn(ax * inv, ay * inv);
    __half2 o1 = __floats2half2_rn(az * inv, aw * inv);
    uint2 p;
    p.x = *(u32*)&o0; p.y = *(u32*)&o1;
    *(uint2*)(out + (size_t)w * DH + lo) = p;
}

// ---------------- MMA primitives ---------------------------------------------
__device__ __forceinline__ void ldm_x4(u32& r0, u32& r1, u32& r2, u32& r3, u32 addr) {
    asm volatile("ldmatrix.sync.aligned.m8n8.x4.shared.b16 {%0,%1,%2,%3}, [%4];"
                 : "=r"(r0), "=r"(r1), "=r"(r2), "=r"(r3) : "r"(addr));
}
__device__ __forceinline__ void mma16816(float* c, const u32* a, u32 b0, u32 b1) {
    asm volatile(
        "mma.sync.aligned.m16n8k16.row.col.f32.f16.f16.f32 "
        "{%0,%1,%2,%3},{%4,%5,%6,%7},{%8,%9},{%0,%1,%2,%3};"
        : "+f"(c[0]), "+f"(c[1]), "+f"(c[2]), "+f"(c[3])
        : "r"(a[0]), "r"(a[1]), "r"(a[2]), "r"(a[3]), "r"(b0), "r"(b1));
}

// ---------------- GEMM core: fp16, K=256 in 4 chunks, cp.async 2-buffer -----
// acc += AggH @ Wn + RootH @ Wr   (chunks 0,1 = agg/Wn; 2,3 = root/Wr)
// dsm layout: A0 | A1 | B0 | B1, each TSZ bytes; chunk kc uses buffer kc&1.
__device__ __forceinline__ void gemm_core(
    char* dsm, const __half* __restrict__ AggH, const __half* __restrict__ RootH,
    const u16* __restrict__ Bn, const u16* __restrict__ Br,
    int blockRow, int tid, int lane, int warpR, int warpC,
    float acc[2][8][4])
{
    const u32 a_b[2] = { smem_u32(dsm), smem_u32(dsm + TSZ) };
    const u32 b_b[2] = { smem_u32(dsm + 2 * TSZ), smem_u32(dsm + 3 * TSZ) };
    const int arow = tid >> 1, acol = (tid & 1) * 32;
    const int agrow = blockRow + arow;
    const bool inb = (agrow < NN);
    const size_t arow_off = (size_t)(inb ? agrow : 0) * DH;
    const int asz = inb ? 16 : 0;     // cp.async src-size: 0 -> zero-fill

    auto issue = [&](int kc) {
        const __half* srcF = (kc < 2) ? AggH : RootH;
        const u16*    Bimg = (kc < 2) ? Bn   : Br;
        const int koff = (kc & 1) * 64;
        const int buf = kc & 1;
        u32 adst = a_b[buf] + (u32)(arow * SB + acol) * 2;
        const __half* rp = srcF + arow_off + koff + acol;
#pragma unroll
        for (int j = 0; j < 4; j++) cpa16(adst + j * 16, rp + j * 8, asz);
        u32 bdst = b_b[buf] + (u32)(arow * SB + acol) * 2;
        const u16* bp = Bimg + arow * 128 + koff + acol;
#pragma unroll
        for (int j = 0; j < 4; j++) cpa16(bdst + j * 16, bp + j * 8, 16);
        cpa_commit();
    };

    issue(0);
#pragma unroll
    for (int kc = 0; kc < 4; kc++) {
        if (kc < 3) { issue(kc + 1); cpa_wait<1>(); }
        else        { cpa_wait<0>(); }
        __syncthreads();

        const u32 ab = a_b[kc & 1], bb = b_b[kc & 1];
#pragma unroll
        for (int ks = 0; ks < 4; ks++) {
            int k0 = ks * 16;
            u32 afrag[2][4];
#pragma unroll
            for (int mi = 0; mi < 2; mi++) {
                int rowA = warpR + mi * 16 + (lane & 15);
                int colA = k0 + ((lane >> 4) << 3);
                ldm_x4(afrag[mi][0], afrag[mi][1], afrag[mi][2], afrag[mi][3],
                       ab + (u32)(rowA * SB + colA) * 2);
            }
            u32 bfrag[4][4];
#pragma unroll
            for (int pj = 0; pj < 4; pj++) {
                int nB = warpC + pj * 16 + ((lane >> 4) << 3) + (lane & 7);
                int kB = k0 + (lane & 8);
                ldm_x4(bfrag[pj][0], bfrag[pj][1], bfrag[pj][2], bfrag[pj][3],
                       bb + (u32)(nB * SB + kB) * 2);
            }
#pragma unroll
            for (int mi = 0; mi < 2; mi++)
#pragma unroll
                for (int nj = 0; nj < 8; nj++) {
                    const u32* bp = bfrag[nj >> 1];
                    u32 b0 = (nj & 1) ? bp[2] : bp[0];
                    u32 b1 = (nj & 1) ? bp[3] : bp[1];
                    mma16816(acc[mi][nj], afrag[mi], b0, b1);
                }
        }
        __syncthreads();   // buffer kc&1 free before issue(kc+2) overwrites it
    }
}

// ---------------- GEMM kernel: mid layer (fp16 hidden out) -------------------
__global__ __launch_bounds__(256, 2)
void k_gemm_mid(const __half* __restrict__ AggH, const __half* __restrict__ RootH,
                const u16* __restrict__ Bn, const u16* __restrict__ Br,
                const float* __restrict__ bias, __half* __restrict__ HoutH)
{
    extern __shared__ char dsm[];
    const int tid = threadIdx.x, wid = tid >> 5, lane = tid & 31;
    const int blockRow = blockIdx.x * 128;
    const int warpR = (wid & 3) * 32, warpC = (wid >> 2) * 64;

    float acc[2][8][4];
#pragma unroll
    for (int i = 0; i < 2; i++)
#pragma unroll
        for (int j = 0; j < 8; j++)
#pragma unroll
            for (int q = 0; q < 4; q++) acc[i][j][q] = 0.f;

    gemm_core(dsm, AggH, RootH, Bn, Br, blockRow, tid, lane, warpR, warpC, acc);

    const int g = lane >> 2, tg = lane & 3;
#pragma unroll
    for (int mi = 0; mi < 2; mi++) {
        int row0 = blockRow + warpR + mi * 16 + g;
        int row1 = row0 + 8;
#pragma unroll
        for (int nj = 0; nj < 8; nj++) {
            int col = warpC + nj * 8 + tg * 2;
            float b0v = bias[col], b1v = bias[col + 1];
            if (row0 < NN)
                *(__half2*)(HoutH + (size_t)row0 * DH + col) =
                    __floats2half2_rn(fmaxf(acc[mi][nj][0] + b0v, 0.f),
                                      fmaxf(acc[mi][nj][1] + b1v, 0.f));
            if (row1 < NN)
                *(__half2*)(HoutH + (size_t)row1 * DH + col) =
                    __floats2half2_rn(fmaxf(acc[mi][nj][2] + b0v, 0.f),
                                      fmaxf(acc[mi][nj][3] + b1v, 0.f));
        }
    }
}

// ---------------- GEMM kernel: last layer + fused head -----------------------
__global__ __launch_bounds__(256, 2)
void k_gemm_head(const __half* __restrict__ AggH, const __half* __restrict__ RootH,
                 const u16* __restrict__ Bn, const u16* __restrict__ Br,
                 const float* __restrict__ bias,
                 const float* __restrict__ Wh, const float* __restrict__ bh,
                 float* __restrict__ out)
{
    extern __shared__ char dsm[];
    __shared__ float HeadPart[2][128];
    const int tid = threadIdx.x, wid = tid >> 5, lane = tid & 31;
    const int blockRow = blockIdx.x * 128;
    const int warpR = (wid & 3) * 32, warpC = (wid >> 2) * 64;

    float acc[2][8][4];
#pragma unroll
    for (int i = 0; i < 2; i++)
#pragma unroll
        for (int j = 0; j < 8; j++)
#pragma unroll
            for (int q = 0; q < 4; q++) acc[i][j][q] = 0.f;

    gemm_core(dsm, AggH, RootH, Bn, Br, blockRow, tid, lane, warpR, warpC, acc);

    const int g = lane >> 2, tg = lane & 3;
    float p0[2] = {0.f, 0.f}, p1[2] = {0.f, 0.f};
#pragma unroll
    for (int mi = 0; mi < 2; mi++) {
#pragma unroll
        for (int nj = 0; nj < 8; nj++) {
            int col = warpC + nj * 8 + tg * 2;
            float b0v = bias[col], b1v = bias[col + 1];
            float w0 = Wh[col], w1 = Wh[col + 1];
            p0[mi] += fmaxf(acc[mi][nj][0] + b0v, 0.f) * w0
                    + fmaxf(acc[mi][nj][1] + b1v, 0.f) * w1;
            p1[mi] += fmaxf(acc[mi][nj][2] + b0v, 0.f) * w0
                    + fmaxf(acc[mi][nj][3] + b1v, 0.f) * w1;
        }
    }
#pragma unroll
    for (int off = 1; off <= 2; off <<= 1) {
#pragma unroll
        for (int mi = 0; mi < 2; mi++) {
            p0[mi] += __shfl_xor_sync(0xFFFFFFFFu, p0[mi], off);
            p1[mi] += __shfl_xor_sync(0xFFFFFFFFu, p1[mi], off);
        }
    }
    if (tg == 0) {
#pragma unroll
        for (int mi = 0; mi < 2; mi++) {
            HeadPart[wid >> 2][warpR + mi * 16 + g]     = p0[mi];
            HeadPart[wid >> 2][warpR + mi * 16 + g + 8] = p1[mi];
        }
    }
    __syncthreads();
    if (tid < 128) {
        int r = blockRow + tid;
        if (r < NN) out[r] = HeadPart[0][tid] + HeadPart[1][tid] + bh[0];
    }
}

// ---------------- launch -----------------------------------------------------
extern "C" void kernel_launch(void* const* d_in, const int* in_sizes, int n_in,
                              void* d_out, int out_size) {
    const float* x   = (const float*)d_in[0];
    const int*   ei  = (const int*)  d_in[1];
    const int*   src = ei;
    const int*   dst = ei + NE;
    const float* Wn0 = (const float*)d_in[2];
    const float* Wr0 = (const float*)d_in[3];
    const float* b0  = (const float*)d_in[4];
    const float* Wn1 = (const float*)d_in[5];
    const float* Wr1 = (const float*)d_in[6];
    const float* b1  = (const float*)d_in[7];
    const float* Wh  = (const float*)d_in[8];
    const float* bh  = (const float*)d_in[9];
    float* out = (float*)d_out;

    __half *aggh, *xh, *h1h;
    u16* wimg;
    cudaGetSymbolAddress((void**)&aggh, g_aggh);
    cudaGetSymbolAddress((void**)&xh,   g_xh);
    cudaGetSymbolAddress((void**)&h1h,  g_h1h);
    cudaGetSymbolAddress((void**)&wimg, g_wimg);

    // idempotent, set every call (no static guards allowed)
    cudaFuncSetAttribute(k_gemm_mid,  cudaFuncAttributeMaxDynamicSharedMemorySize, SM_TOTAL);
    cudaFuncSetAttribute(k_gemm_head, cudaFuncAttributeMaxDynamicSharedMemorySize, SM_TOTAL);

    const int NB_N = (NN + 255) / 256;          // 391
    const int NB_E = (NE + 255) / 256;          // 6250 (1 edge/thread, max grid)
    const int NB_W = (NN * 32 + 255) / 256;     // 12500 (warp per node)
    const int NB_P = (NN * DH / 4 + 255) / 256; // 12500 (covers NE and 65536 too)

    // prep (x->fp16, weights, degree count) + CSR build
    k_prep      <<<NB_P, 256>>>(x, dst, Wn0, Wr0, Wn1, Wr1);
    k_scan_block<<<NB_N, 256>>>();
    k_scan_fuse <<<NB_N, 512>>>(NB_N);
    k_scatter   <<<NB_E, 256>>>(src, dst);

    // layer 0
    k_agg     <<<NB_W, 256>>>(xh, aggh);
    k_gemm_mid<<<NTILES, 256, SM_TOTAL>>>(aggh, xh,
        wimg + 0 * 16384, wimg + 1 * 16384, b0, h1h);
    // layer 1 + fused head
    k_agg      <<<NB_W, 256>>>(h1h, aggh);
    k_gemm_head<<<NTILES, 256, SM_TOTAL>>>(aggh, h1h,
        wimg + 2 * 16384, wimg + 3 * 16384, b1, Wh, bh, out);
}

// round 17
// speedup vs baseline: 1.2479x; 1.0657x over previous
#include <cuda_runtime.h>
#include <cuda_fp16.h>
#include <cstdint>

#define NN 100000
#define NE 1600000
#define DH 128
#define NTILES ((NN + 127) / 128)
#define SB 72      // padded smem row stride (fp16): 144B -> conflict-free ldmatrix
#define TSZ 18432  // one 128 x SB fp16 tile image, bytes
#define SM_TOTAL (4 * TSZ)   // A0, A1, B0, B1 (double buffered)

typedef unsigned int u32;
typedef unsigned short u16;

// ---------------- scratch (device globals: no allocation allowed) -----------
__device__ int    g_deg[NN];          // zero-init; re-zeroed by k_scan_fuse each run
__device__ int    g_rowoff[NN];       // shifted CSR: after scatter, rowoff[w] = row-end
__device__ int    g_blocksum[512];
__device__ int    g_csr_src[NE];
__device__ __half g_aggh[(size_t)NN * DH];  // fp16 aggregation result
__device__ __half g_xh  [(size_t)NN * DH];  // fp16 copy of x   (gather + root L0)
__device__ __half g_h1h [(size_t)NN * DH];  // fp16 h1          (gather + root L1)
// 4 fp16 weight images, [n][k] row-major 128x128: Wn0, Wr0, Wn1, Wr1 (transposed)
__device__ u16 g_wimg[4][16384];

__device__ __forceinline__ u32 smem_u32(const void* p) {
    u32 a;
    asm("{ .reg .u64 t; cvta.to.shared.u64 t, %1; cvt.u32.u64 %0, t; }"
        : "=r"(a) : "l"(p));
    return a;
}
__device__ __forceinline__ void cpa16(u32 dst, const void* src, int srcsz) {
    asm volatile("cp.async.ca.shared.global [%0], [%1], 16, %2;"
                 :: "r"(dst), "l"(src), "r"(srcsz) : "memory");
}
__device__ __forceinline__ void cpa_commit() {
    asm volatile("cp.async.commit_group;" ::: "memory");
}
template <int N>
__device__ __forceinline__ void cpa_wait() {
    asm volatile("cp.async.wait_group %0;" :: "n"(N) : "memory");
}

// ---------------- fused prep: x->fp16, weights, edge degree count -----------
// g_deg is zero at entry (zero-init first run; k_scan_fuse re-zeroes every run).
__global__ void k_prep(const float* __restrict__ x, const int* __restrict__ dst,
                       const float* __restrict__ Wn0, const float* __restrict__ Wr0,
                       const float* __restrict__ Wn1, const float* __restrict__ Wr1) {
    int i = blockIdx.x * blockDim.x + threadIdx.x;
    if (i < NN * DH / 4) {                              // x -> fp16 (float4 groups)
        float4 v = *(const float4*)(x + (size_t)i * 4);
        __half2 h0 = __floats2half2_rn(v.x, v.y);
        __half2 h1 = __floats2half2_rn(v.z, v.w);
        uint2 p;
        p.x = *(u32*)&h0; p.y = *(u32*)&h1;
        *(uint2*)(g_xh + (size_t)i * 4) = p;
    }
    if (i < 65536) {                                    // weights: transpose + fp16
        int mat = i >> 14, e = i & 16383;
        int n = e >> 7, k = e & 127;
        const float* W = (mat == 0) ? Wn0 : (mat == 1) ? Wr0 : (mat == 2) ? Wn1 : Wr1;
        g_wimg[mat][n * 128 + k] = __half_as_ushort(__float2half_rn(W[k * 128 + n]));
    }
    if (i < NE) atomicAdd(&g_deg[dst[i]], 1);           // degree count
}

// ---------------- CSR build --------------------------------------------------
__global__ void k_scan_block() {
    __shared__ int s[256];
    int t = threadIdx.x;
    int i = blockIdx.x * 256 + t;
    int v = (i < NN) ? g_deg[i] : 0;
    s[t] = v; __syncthreads();
#pragma unroll
    for (int off = 1; off < 256; off <<= 1) {
        int tv = (t >= off) ? s[t - off] : 0;
        __syncthreads();
        s[t] += tv;
        __syncthreads();
    }
    if (i < NN) g_rowoff[i] = s[t] - v;
    if (t == 255) g_blocksum[blockIdx.x] = s[255];
}
// 391 blocks x 512 threads: every block scans all block sums, applies its own
// offset, and zeroes g_deg for the next graph replay. (No cursor: scatter
// advances g_rowoff in place -> shifted CSR.)
__global__ void k_scan_fuse(int nblocks) {
    __shared__ int s[512];
    int t = threadIdx.x;
    int v = (t < nblocks) ? g_blocksum[t] : 0;
    s[t] = v; __syncthreads();
    for (int off = 1; off < 512; off <<= 1) {
        int tv = (t >= off) ? s[t - off] : 0;
        __syncthreads();
        s[t] += tv;
        __syncthreads();
    }
    int boff = s[blockIdx.x] - g_blocksum[blockIdx.x];   // exclusive prefix
    if (t < 256) {
        int i = blockIdx.x * 256 + t;
        if (i < NN) {
            g_rowoff[i] += boff;
            g_deg[i] = 0;
        }
    }
}
// advances g_rowoff[dst] in place; after completion rowoff[w] = end of row w,
// begin of row w = (w ? rowoff[w-1] : 0).
__global__ void k_scatter(const int* __restrict__ src, const int* __restrict__ dst) {
    int e = blockIdx.x * blockDim.x + threadIdx.x;
    if (e < NE) {
        int p = atomicAdd(&g_rowoff[dst[e]], 1);
        g_csr_src[p] = src[e];
    }
}

// ---------------- mean aggregation: fp16 gather -> fp16 out -----------------
// One warp per node; max CTA count for L2-latency hiding. Independent
// per-edge fp32 accumulation, MLP = 8 (the R12 converged optimum).
__global__ void k_agg(const __half* __restrict__ feat, __half* __restrict__ out) {
    int w    = (blockIdx.x * blockDim.x + threadIdx.x) >> 5;
    int lane = threadIdx.x & 31;
    if (w >= NN) return;
    int beg = (w > 0) ? g_rowoff[w - 1] : 0;
    int end = g_rowoff[w];
    float ax = 0.f, ay = 0.f, az = 0.f, aw = 0.f;
    const size_t lo = (size_t)lane * 4;
    int e = beg;
    for (; e + 8 <= end; e += 8) {                 // MLP = 8 on the gather
        uint2 r[8];
#pragma unroll
        for (int q = 0; q < 8; q++) {
            int s = g_csr_src[e + q];
            r[q] = *(const uint2*)(feat + (size_t)s * DH + lo);
        }
#pragma unroll
        for (int q = 0; q < 8; q++) {
            float2 f0 = __half22float2(*(__half2*)&r[q].x);
            float2 f1 = __half22float2(*(__half2*)&r[q].y);
            ax += f0.x; ay += f0.y; az += f1.x; aw += f1.y;
        }
    }
    if (e + 4 <= end) {                            // one 4-block tail
        uint2 r[4];
#pragma unroll
        for (int q = 0; q < 4; q++) {
            int s = g_csr_src[e + q];
            r[q] = *(const uint2*)(feat + (size_t)s * DH + lo);
        }
#pragma unroll
        for (int q = 0; q < 4; q++) {
            float2 f0 = __half22float2(*(__half2*)&r[q].x);
            float2 f1 = __half22float2(*(__half2*)&r[q].y);
            ax += f0.x; ay += f0.y; az += f1.x; aw += f1.y;
        }
        e += 4;
    }
    for (; e < end; e++) {
        int s0 = g_csr_src[e];
        uint2 r = *(const uint2*)(feat + (size_t)s0 * DH + lo);
        float2 f0 = __half22float2(*(__half2*)&r.x);
        float2 f1 = __half22float2(*(__half2*)&r.y);
        ax += f0.x; ay += f0.y; az += f1.x; aw += f1.y;
    }
    int deg = end - beg;
    float inv = 1.0f / (float)(deg > 1 ? deg : 1);
    __half2 o0 = __floats2half2_rn(ax * inv, ay * inv);
    __half2 o1 = __floats2half2_rn(az * inv, aw * inv);
    uint2 p;
    p.x = *(u32*)&o0; p.y = *(u32*)&o1;
    *(uint2*)(out + (size_t)w * DH + lo) = p;
}

// ---------------- MMA primitives ---------------------------------------------
__device__ __forceinline__ void ldm_x4(u32& r0, u32& r1, u32& r2, u32& r3, u32 addr) {
    asm volatile("ldmatrix.sync.aligned.m8n8.x4.shared.b16 {%0,%1,%2,%3}, [%4];"
                 : "=r"(r0), "=r"(r1), "=r"(r2), "=r"(r3) : "r"(addr));
}
__device__ __forceinline__ void mma16816(float* c, const u32* a, u32 b0, u32 b1) {
    asm volatile(
        "mma.sync.aligned.m16n8k16.row.col.f32.f16.f16.f32 "
        "{%0,%1,%2,%3},{%4,%5,%6,%7},{%8,%9},{%0,%1,%2,%3};"
        : "+f"(c[0]), "+f"(c[1]), "+f"(c[2]), "+f"(c[3])
        : "r"(a[0]), "r"(a[1]), "r"(a[2]), "r"(a[3]), "r"(b0), "r"(b1));
}

// ---------------- GEMM core: fp16, K=256 in 4 chunks, cp.async 2-buffer -----
// acc += AggH @ Wn + RootH @ Wr   (chunks 0,1 = agg/Wn; 2,3 = root/Wr)
// dsm layout: A0 | A1 | B0 | B1, each TSZ bytes; chunk kc uses buffer kc&1.
__device__ __forceinline__ void gemm_core(
    char* dsm, const __half* __restrict__ AggH, const __half* __restrict__ RootH,
    const u16* __restrict__ Bn, const u16* __restrict__ Br,
    int blockRow, int tid, int lane, int warpR, int warpC,
    float acc[2][8][4])
{
    const u32 a_b[2] = { smem_u32(dsm), smem_u32(dsm + TSZ) };
    const u32 b_b[2] = { smem_u32(dsm + 2 * TSZ), smem_u32(dsm + 3 * TSZ) };
    const int arow = tid >> 1, acol = (tid & 1) * 32;
    const int agrow = blockRow + arow;
    const bool inb = (agrow < NN);
    const size_t arow_off = (size_t)(inb ? agrow : 0) * DH;
    const int asz = inb ? 16 : 0;     // cp.async src-size: 0 -> zero-fill

    auto issue = [&](int kc) {
        const __half* srcF = (kc < 2) ? AggH : RootH;
        const u16*    Bimg = (kc < 2) ? Bn   : Br;
        const int koff = (kc & 1) * 64;
        const int buf = kc & 1;
        u32 adst = a_b[buf] + (u32)(arow * SB + acol) * 2;
        const __half* rp = srcF + arow_off + koff + acol;
#pragma unroll
        for (int j = 0; j < 4; j++) cpa16(adst + j * 16, rp + j * 8, asz);
        u32 bdst = b_b[buf] + (u32)(arow * SB + acol) * 2;
        const u16* bp = Bimg + arow * 128 + koff + acol;
#pragma unroll
        for (int j = 0; j < 4; j++) cpa16(bdst + j * 16, bp + j * 8, 16);
        cpa_commit();
    };

    issue(0);
#pragma unroll
    for (int kc = 0; kc < 4; kc++) {
        if (kc < 3) { issue(kc + 1); cpa_wait<1>(); }
        else        { cpa_wait<0>(); }
        __syncthreads();

        const u32 ab = a_b[kc & 1], bb = b_b[kc & 1];
#pragma unroll
        for (int ks = 0; ks < 4; ks++) {
            int k0 = ks * 16;
            u32 afrag[2][4];
#pragma unroll
            for (int mi = 0; mi < 2; mi++) {
                int rowA = warpR + mi * 16 + (lane & 15);
                int colA = k0 + ((lane >> 4) << 3);
                ldm_x4(afrag[mi][0], afrag[mi][1], afrag[mi][2], afrag[mi][3],
                       ab + (u32)(rowA * SB + colA) * 2);
            }
            u32 bfrag[4][4];
#pragma unroll
            for (int pj = 0; pj < 4; pj++) {
                int nB = warpC + pj * 16 + ((lane >> 4) << 3) + (lane & 7);
                int kB = k0 + (lane & 8);
                ldm_x4(bfrag[pj][0], bfrag[pj][1], bfrag[pj][2], bfrag[pj][3],
                       bb + (u32)(nB * SB + kB) * 2);
            }
#pragma unroll
            for (int mi = 0; mi < 2; mi++)
#pragma unroll
                for (int nj = 0; nj < 8; nj++) {
                    const u32* bp = bfrag[nj >> 1];
                    u32 b0 = (nj & 1) ? bp[2] : bp[0];
                    u32 b1 = (nj & 1) ? bp[3] : bp[1];
                    mma16816(acc[mi][nj], afrag[mi], b0, b1);
                }
        }
        __syncthreads();   // buffer kc&1 free before issue(kc+2) overwrites it
    }
}

// ---------------- GEMM kernel: mid layer (fp16 hidden out) -------------------
__global__ __launch_bounds__(256, 2)
void k_gemm_mid(const __half* __restrict__ AggH, const __half* __restrict__ RootH,
                const u16* __restrict__ Bn, const u16* __restrict__ Br,
                const float* __restrict__ bias, __half* __restrict__ HoutH)
{
    extern __shared__ char dsm[];
    const int tid = threadIdx.x, wid = tid >> 5, lane = tid & 31;
    const int blockRow = blockIdx.x * 128;
    const int warpR = (wid & 3) * 32, warpC = (wid >> 2) * 64;

    float acc[2][8][4];
#pragma unroll
    for (int i = 0; i < 2; i++)
#pragma unroll
        for (int j = 0; j < 8; j++)
#pragma unroll
            for (int q = 0; q < 4; q++) acc[i][j][q] = 0.f;

    gemm_core(dsm, AggH, RootH, Bn, Br, blockRow, tid, lane, warpR, warpC, acc);

    const int g = lane >> 2, tg = lane & 3;
#pragma unroll
    for (int mi = 0; mi < 2; mi++) {
        int row0 = blockRow + warpR + mi * 16 + g;
        int row1 = row0 + 8;
#pragma unroll
        for (int nj = 0; nj < 8; nj++) {
            int col = warpC + nj * 8 + tg * 2;
            float b0v = bias[col], b1v = bias[col + 1];
            if (row0 < NN)
                *(__half2*)(HoutH + (size_t)row0 * DH + col) =
                    __floats2half2_rn(fmaxf(acc[mi][nj][0] + b0v, 0.f),
                                      fmaxf(acc[mi][nj][1] + b1v, 0.f));
            if (row1 < NN)
                *(__half2*)(HoutH + (size_t)row1 * DH + col) =
                    __floats2half2_rn(fmaxf(acc[mi][nj][2] + b0v, 0.f),
                                      fmaxf(acc[mi][nj][3] + b1v, 0.f));
        }
    }
}

// ---------------- GEMM kernel: last layer + fused head -----------------------
__global__ __launch_bounds__(256, 2)
void k_gemm_head(const __half* __restrict__ AggH, const __half* __restrict__ RootH,
                 const u16* __restrict__ Bn, const u16* __restrict__ Br,
                 const float* __restrict__ bias,
                 const float* __restrict__ Wh, const float* __restrict__ bh,
                 float* __restrict__ out)
{
    extern __shared__ char dsm[];
    __shared__ float HeadPart[2][128];
    const int tid = threadIdx.x, wid = tid >> 5, lane = tid & 31;
    const int blockRow = blockIdx.x * 128;
    const int warpR = (wid & 3) * 32, warpC = (wid >> 2) * 64;

    float acc[2][8][4];
#pragma unroll
    for (int i = 0; i < 2; i++)
#pragma unroll
        for (int j = 0; j < 8; j++)
#pragma unroll
            for (int q = 0; q < 4; q++) acc[i][j][q] = 0.f;

    gemm_core(dsm, AggH, RootH, Bn, Br, blockRow, tid, lane, warpR, warpC, acc);

    const int g = lane >> 2, tg = lane & 3;
    float p0[2] = {0.f, 0.f}, p1[2] = {0.f, 0.f};
#pragma unroll
    for (int mi = 0; mi < 2; mi++) {
#pragma unroll
        for (int nj = 0; nj < 8; nj++) {
            int col = warpC + nj * 8 + tg * 2;
            float b0v = bias[col], b1v = bias[col + 1];
            float w0 = Wh[col], w1 = Wh[col + 1];
            p0[mi] += fmaxf(acc[mi][nj][0] + b0v, 0.f) * w0
                    + fmaxf(acc[mi][nj][1] + b1v, 0.f) * w1;
            p1[mi] += fmaxf(acc[mi][nj][2] + b0v, 0.f) * w0
                    + fmaxf(acc[mi][nj][3] + b1v, 0.f) * w1;
        }
    }
#pragma unroll
    for (int off = 1; off <= 2; off <<= 1) {
#pragma unroll
        for (int mi = 0; mi < 2; mi++) {
            p0[mi] += __shfl_xor_sync(0xFFFFFFFFu, p0[mi], off);
            p1[mi] += __shfl_xor_sync(0xFFFFFFFFu, p1[mi], off);
        }
    }
    if (tg == 0) {
#pragma unroll
        for (int mi = 0; mi < 2; mi++) {
            HeadPart[wid >> 2][warpR + mi * 16 + g]     = p0[mi];
            HeadPart[wid >> 2][warpR + mi * 16 + g + 8] = p1[mi];
        }
    }
    __syncthreads();
    if (tid < 128) {
        int r = blockRow + tid;
        if (r < NN) out[r] = HeadPart[0][tid] + HeadPart[1][tid] + bh[0];
    }
}

// ---------------- launch -----------------------------------------------------
extern "C" void kernel_launch(void* const* d_in, const int* in_sizes, int n_in,
                              void* d_out, int out_size) {
    const float* x   = (const float*)d_in[0];
    const int*   ei  = (const int*)  d_in[1];
    const int*   src = ei;
    const int*   dst = ei + NE;
    const float* Wn0 = (const float*)d_in[2];
    const float* Wr0 = (const float*)d_in[3];
    const float* b0  = (const float*)d_in[4];
    const float* Wn1 = (const float*)d_in[5];
    const float* Wr1 = (const float*)d_in[6];
    const float* b1  = (const float*)d_in[7];
    const float* Wh  = (const float*)d_in[8];
    const float* bh  = (const float*)d_in[9];
    float* out = (float*)d_out;

    __half *aggh, *xh, *h1h;
    u16* wimg;
    cudaGetSymbolAddress((void**)&aggh, g_aggh);
    cudaGetSymbolAddress((void**)&xh,   g_xh);
    cudaGetSymbolAddress((void**)&h1h,  g_h1h);
    cudaGetSymbolAddress((void**)&wimg, g_wimg);

    // idempotent, set every call (no static guards allowed)
    cudaFuncSetAttribute(k_gemm_mid,  cudaFuncAttributeMaxDynamicSharedMemorySize, SM_TOTAL);
    cudaFuncSetAttribute(k_gemm_head, cudaFuncAttributeMaxDynamicSharedMemorySize, SM_TOTAL);

    const int NB_N = (NN + 255) / 256;          // 391
    const int NB_E = (NE + 255) / 256;          // 6250
    const int NB_W = (NN * 32 + 255) / 256;     // 12500 (warp per node)
    const int NB_P = (NN * DH / 4 + 255) / 256; // 12500 (covers NE and 65536 too)

    // prep (x->fp16, weights, degree count) + CSR build
    k_prep      <<<NB_P, 256>>>(x, dst, Wn0, Wr0, Wn1, Wr1);
    k_scan_block<<<NB_N, 256>>>();
    k_scan_fuse <<<NB_N, 512>>>(NB_N);
    k_scatter   <<<NB_E, 256>>>(src, dst);

    // layer 0
    k_agg     <<<NB_W, 256>>>(xh, aggh);
    k_gemm_mid<<<NTILES, 256, SM_TOTAL>>>(aggh, xh,
        wimg + 0 * 16384, wimg + 1 * 16384, b0, h1h);
    // layer 1 + fused head
    k_agg      <<<NB_W, 256>>>(h1h, aggh);
    k_gemm_head<<<NTILES, 256, SM_TOTAL>>>(aggh, h1h,
        wimg + 2 * 16384, wimg + 3 * 16384, b1, Wh, bh, out);
}